// round 5
// baseline (speedup 1.0000x reference)
#include <cuda_runtime.h>

#define TPB    192        // one thread per 8 floats of a 1536-float row
#define BAND   32         // output rows per block
#define HH     384
#define ROWF   1536       // W*C floats per row
#define NBANDS (HH / BAND)

static __device__ __forceinline__ int hrefl(int h) {
    // reflect-101 along height; used only for h in [-2, HH+1]
    h = (h < 0) ? -h : h;
    return (h >= HH) ? (2 * HH - 2 - h) : h;
}

// Gaussian taps for ksize=5, sigma=1.1 (OpenCV default), normalized.
#define C0 0.07076630f    /* w[0] = w[4] */
#define C1 0.24446028f    /* w[1] = w[3] */
#define C2 0.36954642f    /* w[2]        */

struct F8  { float v[8]; };
struct Raw { float4 C, D; float e[6]; };   // e = cross-warp halo (lanes 0/31 only)

// LOAD STAGE: fetch this thread's 8 floats of row h plus (for warp-edge
// lanes) the 6-float cross-warp halo. No shuffles, no dependent compute.
static __device__ __forceinline__ Raw load_raw(
    const float* __restrict__ ib, int h, int t, int lane)
{
    const float* __restrict__ rp = ib + (long)hrefl(h) * ROWF + 8 * t;
    Raw r;
    r.C = *(const float4*)(rp);       // flats 8t   .. 8t+3
    r.D = *(const float4*)(rp + 4);   // flats 8t+4 .. 8t+7
    if (lane == 0 && t > 0) {         // left halo: flats 8t-6 .. 8t-1
        float2 a = *(const float2*)(rp - 6);
        float4 b = *(const float4*)(rp - 4);
        r.e[0] = a.x; r.e[1] = a.y; r.e[2] = b.x;
        r.e[3] = b.y; r.e[4] = b.z; r.e[5] = b.w;
    } else if (lane == 31 && t < TPB - 1) {  // right halo: flats 8t+8 .. 8t+13
        float4 b = *(const float4*)(rp + 8);
        float2 a = *(const float2*)(rp + 12);
        r.e[0] = b.x; r.e[1] = b.y; r.e[2] = b.z;
        r.e[3] = b.w; r.e[4] = a.x; r.e[5] = a.y;
    }
    return r;
}

// COMPUTE STAGE: horizontal blur of the 8 floats using shuffles for the
// intra-warp halo, r.e for warp edges, register permutation for image edges.
static __device__ __forceinline__ F8 hb_compute(const Raw& r, int t, int lane)
{
    const float4 Cb = r.C, Db = r.D;

    // e[k] = flat(8t - 6 + k), k = 0..19
    float e0  = __shfl_up_sync(0xffffffffu, Cb.z, 1);
    float e1  = __shfl_up_sync(0xffffffffu, Cb.w, 1);
    float e2  = __shfl_up_sync(0xffffffffu, Db.x, 1);
    float e3  = __shfl_up_sync(0xffffffffu, Db.y, 1);
    float e4  = __shfl_up_sync(0xffffffffu, Db.z, 1);
    float e5  = __shfl_up_sync(0xffffffffu, Db.w, 1);
    float e14 = __shfl_down_sync(0xffffffffu, Cb.x, 1);
    float e15 = __shfl_down_sync(0xffffffffu, Cb.y, 1);
    float e16 = __shfl_down_sync(0xffffffffu, Cb.z, 1);
    float e17 = __shfl_down_sync(0xffffffffu, Cb.w, 1);
    float e18 = __shfl_down_sync(0xffffffffu, Db.x, 1);
    float e19 = __shfl_down_sync(0xffffffffu, Db.y, 1);

    if (lane == 0 && t > 0) {
        e0 = r.e[0]; e1 = r.e[1]; e2 = r.e[2];
        e3 = r.e[3]; e4 = r.e[4]; e5 = r.e[5];
    }
    if (lane == 31 && t < TPB - 1) {
        e14 = r.e[0]; e15 = r.e[1]; e16 = r.e[2];
        e17 = r.e[3]; e18 = r.e[4]; e19 = r.e[5];
    }
    if (t == 0) {            // flats -6..-1 -> reflected {6,7,8,3,4,5}
        e0 = Db.z; e1 = Db.w; e2 = e14; e3 = Cb.w; e4 = Db.x; e5 = Db.y;
    }
    if (t == TPB - 1) {      // flats 1536..1541 -> {1530,1531,1532,1527,1528,1529}
        e14 = Cb.z; e15 = Cb.w; e16 = Db.x; e17 = e5; e18 = Cb.x; e19 = Cb.y;
    }

    const float e6 = Cb.x, e7 = Cb.y, e8 = Cb.z, e9 = Cb.w;
    const float e10 = Db.x, e11 = Db.y, e12 = Db.z, e13 = Db.w;

    // Horizontal taps at flat offsets {-6,-3,0,+3,+6}.
    F8 o;
    o.v[0] = C0 * (e0 + e12) + C1 * (e3  + e9)  + C2 * e6;
    o.v[1] = C0 * (e1 + e13) + C1 * (e4  + e10) + C2 * e7;
    o.v[2] = C0 * (e2 + e14) + C1 * (e5  + e11) + C2 * e8;
    o.v[3] = C0 * (e3 + e15) + C1 * (e6  + e12) + C2 * e9;
    o.v[4] = C0 * (e4 + e16) + C1 * (e7  + e13) + C2 * e10;
    o.v[5] = C0 * (e5 + e17) + C1 * (e8  + e14) + C2 * e11;
    o.v[6] = C0 * (e6 + e18) + C1 * (e9  + e15) + C2 * e12;
    o.v[7] = C0 * (e7 + e19) + C1 * (e10 + e16) + C2 * e13;
    return o;
}

__global__ void __launch_bounds__(TPB, 3)
gauss5_kernel(const float* __restrict__ x, float* __restrict__ y)
{
    const int t    = threadIdx.x;
    const int lane = t & 31;
    const int h0   = blockIdx.x * BAND;
    const long img = blockIdx.y;

    const float* __restrict__ ib = x + img * (long)(HH * ROWF);
    float*       __restrict__ ob = y + img * (long)(HH * ROWF) + 8 * t;

    // Prologue: 5-row sliding window of horizontally-blurred values.
    F8 w0 = hb_compute(load_raw(ib, h0 - 2, t, lane), t, lane);
    F8 w1 = hb_compute(load_raw(ib, h0 - 1, t, lane), t, lane);
    F8 w2 = hb_compute(load_raw(ib, h0,     t, lane), t, lane);
    F8 w3 = hb_compute(load_raw(ib, h0 + 1, t, lane), t, lane);
    Raw cur = load_raw(ib, h0 + 2, t, lane);   // raw row r+2, compute deferred

    #pragma unroll 4
    for (int r = 0; r < BAND; r++) {
        // Issue next row's loads BEFORE the dependent shuffle/FMA work:
        // load-to-use distance = one full iteration.
        Raw nxt = load_raw(ib, h0 + r + 3, t, lane);

        F8 w4 = hb_compute(cur, t, lane);

        // Vertical pass (symmetric taps), thread-private.
        float4 oa, obv;
        oa.x  = C0 * (w0.v[0] + w4.v[0]) + C1 * (w1.v[0] + w3.v[0]) + C2 * w2.v[0];
        oa.y  = C0 * (w0.v[1] + w4.v[1]) + C1 * (w1.v[1] + w3.v[1]) + C2 * w2.v[1];
        oa.z  = C0 * (w0.v[2] + w4.v[2]) + C1 * (w1.v[2] + w3.v[2]) + C2 * w2.v[2];
        oa.w  = C0 * (w0.v[3] + w4.v[3]) + C1 * (w1.v[3] + w3.v[3]) + C2 * w2.v[3];
        obv.x = C0 * (w0.v[4] + w4.v[4]) + C1 * (w1.v[4] + w3.v[4]) + C2 * w2.v[4];
        obv.y = C0 * (w0.v[5] + w4.v[5]) + C1 * (w1.v[5] + w3.v[5]) + C2 * w2.v[5];
        obv.z = C0 * (w0.v[6] + w4.v[6]) + C1 * (w1.v[6] + w3.v[6]) + C2 * w2.v[6];
        obv.w = C0 * (w0.v[7] + w4.v[7]) + C1 * (w1.v[7] + w3.v[7]) + C2 * w2.v[7];

        float4* op = (float4*)(ob + (long)(h0 + r) * ROWF);
        op[0] = oa;
        op[1] = obv;

        w0 = w1; w1 = w2; w2 = w3; w3 = w4;
        cur = nxt;
    }
}

extern "C" void kernel_launch(void* const* d_in, const int* in_sizes, int n_in,
                              void* d_out, int out_size)
{
    const float* x = (const float*)d_in[0];
    float* y = (float*)d_out;
    const int batch = in_sizes[0] / (HH * ROWF);   // 64
    dim3 grid(NBANDS, batch);
    gauss5_kernel<<<grid, TPB>>>(x, y);
}